// round 6
// baseline (speedup 1.0000x reference)
#include <cuda_runtime.h>
#include <cstdint>

// Problem constants (fixed by the dataset): E=1e6, N=1e5, D=128, H=128, CIN=384.
#define DIM       128
#define TILE      128
#define LDA       132      // 132 % 4 == 0 -> float4-aligned rows, conflict-free frag loads
#define NTHREADS  256

#define N_PAD_ROWS 100096  // 782 * 128, lets precompute store full tiles unguarded

// Scratch: P = nfeat @ W1[128:256], Q = nfeat @ W1[256:384]   (~51 MB each, static = legal)
__device__ float g_P[(size_t)N_PAD_ROWS * DIM];
__device__ float g_Q[(size_t)N_PAD_ROWS * DIM];

// ---------------------------------------------------------------------------
// tf32 helpers
// ---------------------------------------------------------------------------
__device__ __forceinline__ uint32_t f2tf32(float x) {
    uint32_t u;
    asm("cvt.rna.tf32.f32 %0, %1;" : "=r"(u) : "f"(x));
    return u;
}

__device__ __forceinline__ void mma_tf32(float* c, const uint32_t* a, const uint32_t* b) {
    asm volatile(
        "mma.sync.aligned.m16n8k8.row.col.f32.tf32.tf32.f32 "
        "{%0,%1,%2,%3}, {%4,%5,%6,%7}, {%8,%9}, {%0,%1,%2,%3};\n"
        : "+f"(c[0]), "+f"(c[1]), "+f"(c[2]), "+f"(c[3])
        : "r"(a[0]), "r"(a[1]), "r"(a[2]), "r"(a[3]), "r"(b[0]), "r"(b[1]));
}

// 128x128x128 GEMM from smem. A: fp32 (converted at read). B: pre-converted tf32 bits.
// Warp (wm,wn): rows [wm*32, +32), cols [wn*64, +64).
// Accum c[mi][ni][j]: row = wm*32 + mi*16 + g + (j>=2 ? 8 : 0),
//                     col = wn*64 + ni*8 + 2t + (j&1),  g=lane/4, t=lane%4.
__device__ __forceinline__ void gemm128(const float* __restrict__ As,
                                        const float* __restrict__ Bs,
                                        float c[2][8][4], int wm, int wn, int g, int t) {
#pragma unroll
    for (int kk = 0; kk < 128; kk += 8) {
        uint32_t a[2][4];
#pragma unroll
        for (int mi = 0; mi < 2; mi++) {
            int r0 = wm * 32 + mi * 16;
            a[mi][0] = f2tf32(As[(r0 + g) * LDA + kk + t]);
            a[mi][1] = f2tf32(As[(r0 + g + 8) * LDA + kk + t]);
            a[mi][2] = f2tf32(As[(r0 + g) * LDA + kk + t + 4]);
            a[mi][3] = f2tf32(As[(r0 + g + 8) * LDA + kk + t + 4]);
        }
#pragma unroll
        for (int ni = 0; ni < 8; ni++) {
            uint32_t b[2];
            int col = wn * 64 + ni * 8 + g;
            b[0] = __float_as_uint(Bs[(kk + t) * LDA + col]);
            b[1] = __float_as_uint(Bs[(kk + t + 4) * LDA + col]);
            mma_tf32(c[0][ni], a[0], b);
            mma_tf32(c[1][ni], a[1], b);
        }
    }
}

__device__ __forceinline__ void zero_acc(float c[2][8][4]) {
#pragma unroll
    for (int mi = 0; mi < 2; mi++)
#pragma unroll
        for (int ni = 0; ni < 8; ni++)
#pragma unroll
            for (int j = 0; j < 4; j++) c[mi][ni][j] = 0.f;
}

__device__ __forceinline__ void fill_tile_f32(float* __restrict__ dst,
                                              const float* __restrict__ src,
                                              int rows_valid, int tid) {
    for (int i = tid; i < 128 * 32; i += NTHREADS) {
        int r = i >> 5, c4 = (i & 31) << 2;
        float4 v = make_float4(0.f, 0.f, 0.f, 0.f);
        if (r < rows_valid) v = *(const float4*)(src + (size_t)r * DIM + c4);
        *(float4*)(dst + r * LDA + c4) = v;
    }
}

__device__ __forceinline__ void fill_tile_tf32(float* __restrict__ dst,
                                               const float* __restrict__ src, int tid) {
    for (int i = tid; i < 128 * 32; i += NTHREADS) {
        int r = i >> 5, c4 = (i & 31) << 2;
        float4 v = *(const float4*)(src + (size_t)r * DIM + c4);
        v.x = __uint_as_float(f2tf32(v.x));
        v.y = __uint_as_float(f2tf32(v.y));
        v.z = __uint_as_float(f2tf32(v.z));
        v.w = __uint_as_float(f2tf32(v.w));
        *(float4*)(dst + r * LDA + c4) = v;
    }
}

// ---------------------------------------------------------------------------
// Kernel A: P = nfeat @ W1b, Q = nfeat @ W1c
// ---------------------------------------------------------------------------
__global__ void __launch_bounds__(NTHREADS, 1)
precompute_pq(const float* __restrict__ nfeat, const float* __restrict__ W1, int N) {
    extern __shared__ float sm[];
    float* As = sm;
    float* Bs = sm + 128 * LDA;

    int tid = threadIdx.x;
    int lane = tid & 31, w = tid >> 5;
    int wm = w & 3, wn = w >> 2, g = lane >> 2, t = lane & 3;
    int n0 = blockIdx.x * TILE;
    int valid = min(TILE, N - n0);

    fill_tile_f32(As, nfeat + (size_t)n0 * DIM, valid, tid);
    fill_tile_tf32(Bs, W1 + 128 * DIM, tid);  // W1b (src part)
    __syncthreads();

    float c[2][8][4];
    zero_acc(c);
    gemm128(As, Bs, c, wm, wn, g, t);

    float* P = g_P + (size_t)n0 * DIM;
#pragma unroll
    for (int mi = 0; mi < 2; mi++)
#pragma unroll
        for (int h = 0; h < 2; h++) {
            int r = wm * 32 + mi * 16 + g + h * 8;
#pragma unroll
            for (int ni = 0; ni < 8; ni++) {
                int col = wn * 64 + ni * 8 + 2 * t;
                *(float2*)(P + (size_t)r * DIM + col) =
                    make_float2(c[mi][ni][h * 2], c[mi][ni][h * 2 + 1]);
            }
        }

    __syncthreads();
    fill_tile_tf32(Bs, W1 + 256 * DIM, tid);   // W1c (dst part)
    __syncthreads();

    zero_acc(c);
    gemm128(As, Bs, c, wm, wn, g, t);

    float* Q = g_Q + (size_t)n0 * DIM;
#pragma unroll
    for (int mi = 0; mi < 2; mi++)
#pragma unroll
        for (int h = 0; h < 2; h++) {
            int r = wm * 32 + mi * 16 + g + h * 8;
#pragma unroll
            for (int ni = 0; ni < 8; ni++) {
                int col = wn * 64 + ni * 8 + 2 * t;
                *(float2*)(Q + (size_t)r * DIM + col) =
                    make_float2(c[mi][ni][h * 2], c[mi][ni][h * 2 + 1]);
            }
        }
}

// ---------------------------------------------------------------------------
// Kernel B: per-edge fused MLP
// ---------------------------------------------------------------------------
__global__ void __launch_bounds__(NTHREADS, 1)
edge_mlp(const float* __restrict__ efeat, const float* __restrict__ W1,
         const float* __restrict__ b1, const float* __restrict__ W2,
         const float* __restrict__ b2, const float* __restrict__ lng,
         const float* __restrict__ lnb, const int* __restrict__ src_idx,
         const int* __restrict__ dst_idx, float* __restrict__ out, int E, int N) {
    extern __shared__ float sm[];
    float* As = sm;                       // efeat tile (raw fp32, kept for residual)
    float* Bs = sm + 128 * LDA;           // W1a then W2 (tf32 bits)
    float* Hs = sm + 2 * 128 * LDA;       // PQ staging, then h
    int*   s_src = (int*)(sm + 3 * 128 * LDA);  // +512 B
    int*   s_dst = s_src + 128;                 // +512 B
    float* s_b1  = (float*)(s_dst + 128);       // +512 B
    float* s_b2  = s_b1 + 128;                  // +512 B
    float* s_lng = s_b2 + 128;                  // +512 B
    float* s_lnb = s_lng + 128;                 // +512 B
    float* s_sum = s_lnb + 128;                 // [2][128] -> +1024 B
    float* s_ssq = s_sum + 256;                 // [2][128] -> +1024 B

    int tid = threadIdx.x;
    int lane = tid & 31, w = tid >> 5;
    int wm = w & 3, wn = w >> 2, g = lane >> 2, t = lane & 3;
    int e0 = blockIdx.x * TILE;
    int valid = min(TILE, E - e0);

    if (tid < 128) {
        int e = e0 + tid;
        int si = (tid < valid) ? src_idx[e] : 0;
        int di = (tid < valid) ? dst_idx[e] : 0;
        // clamp: garbage indices degrade accuracy instead of trapping
        s_src[tid] = (si >= 0 && si < N) ? si : 0;
        s_dst[tid] = (di >= 0 && di < N) ? di : 0;
        s_b1[tid]  = b1[tid];
        s_b2[tid]  = b2[tid];
        s_lng[tid] = lng[tid];
        s_lnb[tid] = lnb[tid];
    }
    fill_tile_f32(As, efeat + (size_t)e0 * DIM, valid, tid);
    fill_tile_tf32(Bs, W1, tid);          // W1a (rows 0..127)
    __syncthreads();

    // Stage PQ[r][c] = P[src[r]][c] + Q[dst[r]][c] + b1[c] into Hs.
    for (int i = tid; i < 128 * 32; i += NTHREADS) {
        int r = i >> 5, c4 = (i & 31) << 2;
        float4 p = *(const float4*)(g_P + (size_t)s_src[r] * DIM + c4);
        float4 q = *(const float4*)(g_Q + (size_t)s_dst[r] * DIM + c4);
        float4 bb = *(const float4*)(s_b1 + c4);
        float4 v;
        v.x = p.x + q.x + bb.x;
        v.y = p.y + q.y + bb.y;
        v.z = p.z + q.z + bb.z;
        v.w = p.w + q.w + bb.w;
        *(float4*)(Hs + r * LDA + c4) = v;
    }
    __syncthreads();

    float c[2][8][4];
    zero_acc(c);
    gemm128(As, Bs, c, wm, wn, g, t);     // GEMM1 edge part

    // silu(frag + PQ) -> overwrite Hs at SAME (r,c) this thread owns (no race).
#pragma unroll
    for (int mi = 0; mi < 2; mi++)
#pragma unroll
        for (int ni = 0; ni < 8; ni++)
#pragma unroll
            for (int h = 0; h < 2; h++) {
                int r = wm * 32 + mi * 16 + g + h * 8;
                int col = wn * 64 + ni * 8 + 2 * t;
                float2 pq = *(float2*)(Hs + r * LDA + col);
                float x0 = c[mi][ni][h * 2] + pq.x;
                float x1 = c[mi][ni][h * 2 + 1] + pq.y;
                float s0 = x0 / (1.f + __expf(-x0));
                float s1 = x1 / (1.f + __expf(-x1));
                *(float2*)(Hs + r * LDA + col) = make_float2(s0, s1);
            }
    __syncthreads();
    fill_tile_tf32(Bs, W2, tid);
    __syncthreads();

    zero_acc(c);
    gemm128(Hs, Bs, c, wm, wn, g, t);     // GEMM2

    float psum[2][2] = {{0.f, 0.f}, {0.f, 0.f}};
    float pssq[2][2] = {{0.f, 0.f}, {0.f, 0.f}};
#pragma unroll
    for (int mi = 0; mi < 2; mi++)
#pragma unroll
        for (int ni = 0; ni < 8; ni++)
#pragma unroll
            for (int j = 0; j < 4; j++) {
                int col = wn * 64 + ni * 8 + 2 * t + (j & 1);
                float v = c[mi][ni][j] + s_b2[col];
                c[mi][ni][j] = v;
                psum[mi][j >> 1] += v;
                pssq[mi][j >> 1] += v * v;
            }
#pragma unroll
    for (int mi = 0; mi < 2; mi++)
#pragma unroll
        for (int h = 0; h < 2; h++) {
            float s = psum[mi][h], q = pssq[mi][h];
            s += __shfl_xor_sync(0xffffffffu, s, 1);
            s += __shfl_xor_sync(0xffffffffu, s, 2);
            q += __shfl_xor_sync(0xffffffffu, q, 1);
            q += __shfl_xor_sync(0xffffffffu, q, 2);
            if (t == 0) {
                int r = wm * 32 + mi * 16 + g + h * 8;
                s_sum[wn * 128 + r] = s;
                s_ssq[wn * 128 + r] = q;
            }
        }
    __syncthreads();

#pragma unroll
    for (int mi = 0; mi < 2; mi++)
#pragma unroll
        for (int h = 0; h < 2; h++) {
            int r = wm * 32 + mi * 16 + g + h * 8;
            float sum = s_sum[r] + s_sum[128 + r];
            float ssq = s_ssq[r] + s_ssq[128 + r];
            float mean = sum * (1.f / 128.f);
            float var = ssq * (1.f / 128.f) - mean * mean;
            float rstd = rsqrtf(var + 1e-5f);
            if (r < valid) {
#pragma unroll
                for (int ni = 0; ni < 8; ni++) {
                    int col = wn * 64 + ni * 8 + 2 * t;
                    float2 ef = *(float2*)(As + r * LDA + col);
                    float y0 = (c[mi][ni][h * 2] - mean) * rstd * s_lng[col] +
                               s_lnb[col] + ef.x;
                    float y1 = (c[mi][ni][h * 2 + 1] - mean) * rstd * s_lng[col + 1] +
                               s_lnb[col + 1] + ef.y;
                    *(float2*)(out + (size_t)(e0 + r) * DIM + col) = make_float2(y0, y1);
                }
            }
        }
}

// ---------------------------------------------------------------------------
// Launch: size-based input identification (robust to metadata ordering)
// ---------------------------------------------------------------------------
extern "C" void kernel_launch(void* const* d_in, const int* in_sizes, int n_in,
                              void* d_out, int out_size) {
    // Expected element counts: efeat E*128 (max), nfeat N*128, src/dst E (x2),
    // W1 49152, W2 16384, b1/b2/ln_g/ln_b 128 (x4).
    long long maxsz = 0;
    for (int i = 0; i < n_in; i++)
        if ((long long)in_sizes[i] > maxsz) maxsz = in_sizes[i];
    long long E = maxsz / DIM;

    int i_efeat = -1, i_nfeat = -1, i_W1 = -1, i_W2 = -1;
    int idxArr[2] = {-1, -1};  int nIdx = 0;         // size-E arrays, in order
    int vecArr[4] = {-1, -1, -1, -1}; int nVec = 0;  // size-128 arrays, in order
    for (int i = 0; i < n_in; i++) {
        long long s = in_sizes[i];
        if (s == maxsz)              i_efeat = i;
        else if (s == 3 * 128 * 128) i_W1 = i;
        else if (s == 128 * 128)     i_W2 = i;
        else if (s == 128)           { if (nVec < 4) vecArr[nVec++] = i; }
        else if (s == E)             { if (nIdx < 2) idxArr[nIdx++] = i; }
        else                         i_nfeat = i;  // N*128
    }
    // Layout detection: alphabetical puts W1 first; insertion puts efeat first.
    bool alpha = (i_W1 == 0);
    // insertion: src,dst then b1,b2,ln_g,ln_b.  alpha: dst,src then b1,b2,ln_b,ln_g.
    int i_src = alpha ? idxArr[1] : idxArr[0];
    int i_dst = alpha ? idxArr[0] : idxArr[1];
    int i_b1 = vecArr[0], i_b2 = vecArr[1];
    int i_lng = alpha ? vecArr[3] : vecArr[2];
    int i_lnb = alpha ? vecArr[2] : vecArr[3];

    const float* efeat = (const float*)d_in[i_efeat];
    const float* nfeat = (const float*)d_in[i_nfeat];
    const int* src_idx = (const int*)d_in[i_src];
    const int* dst_idx = (const int*)d_in[i_dst];
    const float* W1 = (const float*)d_in[i_W1];
    const float* b1 = (const float*)d_in[i_b1];
    const float* W2 = (const float*)d_in[i_W2];
    const float* b2 = (const float*)d_in[i_b2];
    const float* lng = (const float*)d_in[i_lng];
    const float* lnb = (const float*)d_in[i_lnb];
    float* out = (float*)d_out;

    int Ei = (int)E;
    int N = in_sizes[i_nfeat] / DIM;

    const int SMEM_A = 2 * 128 * LDA * (int)sizeof(float);       // 135168 B
    // Tail: s_src/s_dst 2*512 + 4 param vecs 4*512 + s_sum/s_ssq 2*1024 = 5120 B
    const int SMEM_B = 3 * 128 * LDA * (int)sizeof(float) + 5120; // 207872 B

    cudaFuncSetAttribute(precompute_pq, cudaFuncAttributeMaxDynamicSharedMemorySize, SMEM_A);
    cudaFuncSetAttribute(edge_mlp, cudaFuncAttributeMaxDynamicSharedMemorySize, SMEM_B);

    // Guard precompute store range against g_P/g_Q capacity.
    int nBlocks = (N + TILE - 1) / TILE;
    if ((long long)nBlocks * TILE > N_PAD_ROWS) nBlocks = N_PAD_ROWS / TILE;

    precompute_pq<<<nBlocks, NTHREADS, SMEM_A>>>(nfeat, W1, N);
    edge_mlp<<<(Ei + TILE - 1) / TILE, NTHREADS, SMEM_B>>>(
        efeat, W1, b1, W2, b2, lng, lnb, src_idx, dst_idx, out, Ei, N);

    // nfeat passthrough only if the output buffer actually holds the tuple.
    long long need = E * DIM + (long long)N * DIM;
    if ((long long)out_size >= need) {
        cudaMemcpyAsync(out + (size_t)E * DIM, nfeat,
                        (size_t)N * DIM * sizeof(float), cudaMemcpyDeviceToDevice);
    }
}

// round 7
// speedup vs baseline: 1.3756x; 1.3756x over previous
#include <cuda_runtime.h>
#include <cstdint>

// Problem constants: E=1e6, N=1e5, D=128, H=128, CIN=384.
#define DIM       128
#define TILE      128
#define LDA       132      // pitch: conflict-free A-frag loads, float4-aligned
#define NT_PRE    256
#define NT_EDGE   512

#define N_PAD_ROWS 100096  // 782 * 128

__device__ float g_P[(size_t)N_PAD_ROWS * DIM];
__device__ float g_Q[(size_t)N_PAD_ROWS * DIM];

// ---------------------------------------------------------------------------
__device__ __forceinline__ uint32_t f2tf32(float x) {
    uint32_t u;
    asm("cvt.rna.tf32.f32 %0, %1;" : "=r"(u) : "f"(x));
    return u;
}

__device__ __forceinline__ void mma_tf32(float* c, const uint32_t* a, const uint32_t* b) {
    asm volatile(
        "mma.sync.aligned.m16n8k8.row.col.f32.tf32.tf32.f32 "
        "{%0,%1,%2,%3}, {%4,%5,%6,%7}, {%8,%9}, {%0,%1,%2,%3};\n"
        : "+f"(c[0]), "+f"(c[1]), "+f"(c[2]), "+f"(c[3])
        : "r"(a[0]), "r"(a[1]), "r"(a[2]), "r"(a[3]), "r"(b[0]), "r"(b[1]));
}

// ---------------------------------------------------------------------------
// 32x32 warp-tile GEMM over 128-K from smem (16-warp version).
// Warp (wm,wn): rows [wm*32,+32), cols [wn*32,+32).
// c[mi][ni][j]: row = wm*32 + mi*16 + g + (j>=2?8:0), col = wn*32 + ni*8 + 2t + (j&1).
// A-frag LDS banks: (r0+g)*132 + kk + t -> bank g*4+t: all 32 distinct, conflict-free.
template <bool CVT_A>
__device__ __forceinline__ void gemm_tile(const float* __restrict__ As,
                                          const float* __restrict__ Bs,
                                          float c[2][4][4], int wm, int wn, int g, int t) {
#pragma unroll
    for (int kk = 0; kk < 128; kk += 8) {
        uint32_t a[2][4];
#pragma unroll
        for (int mi = 0; mi < 2; mi++) {
            int r0 = wm * 32 + mi * 16;
            const float* p0 = As + (r0 + g) * LDA + kk + t;
            const float* p1 = As + (r0 + g + 8) * LDA + kk + t;
            if (CVT_A) {
                a[mi][0] = f2tf32(p0[0]);
                a[mi][1] = f2tf32(p1[0]);
                a[mi][2] = f2tf32(p0[4]);
                a[mi][3] = f2tf32(p1[4]);
            } else {
                a[mi][0] = __float_as_uint(p0[0]);
                a[mi][1] = __float_as_uint(p1[0]);
                a[mi][2] = __float_as_uint(p0[4]);
                a[mi][3] = __float_as_uint(p1[4]);
            }
        }
#pragma unroll
        for (int ni = 0; ni < 4; ni++) {
            uint32_t b[2];
            int col = wn * 32 + ni * 8 + g;
            b[0] = __float_as_uint(Bs[(kk + t) * LDA + col]);
            b[1] = __float_as_uint(Bs[(kk + t + 4) * LDA + col]);
            mma_tf32(c[0][ni], a[0], b);
            mma_tf32(c[1][ni], a[1], b);
        }
    }
}

__device__ __forceinline__ void zero_acc4(float c[2][4][4]) {
#pragma unroll
    for (int mi = 0; mi < 2; mi++)
#pragma unroll
        for (int ni = 0; ni < 4; ni++)
#pragma unroll
            for (int j = 0; j < 4; j++) c[mi][ni][j] = 0.f;
}

// 64-wide warp-tile version for precompute (8 warps, 32x64 tiles)
__device__ __forceinline__ void gemm128_pre(const float* __restrict__ As,
                                            const float* __restrict__ Bs,
                                            float c[2][8][4], int wm, int wn, int g, int t) {
#pragma unroll
    for (int kk = 0; kk < 128; kk += 8) {
        uint32_t a[2][4];
#pragma unroll
        for (int mi = 0; mi < 2; mi++) {
            int r0 = wm * 32 + mi * 16;
            a[mi][0] = f2tf32(As[(r0 + g) * LDA + kk + t]);
            a[mi][1] = f2tf32(As[(r0 + g + 8) * LDA + kk + t]);
            a[mi][2] = f2tf32(As[(r0 + g) * LDA + kk + t + 4]);
            a[mi][3] = f2tf32(As[(r0 + g + 8) * LDA + kk + t + 4]);
        }
#pragma unroll
        for (int ni = 0; ni < 8; ni++) {
            uint32_t b[2];
            int col = wn * 64 + ni * 8 + g;
            b[0] = __float_as_uint(Bs[(kk + t) * LDA + col]);
            b[1] = __float_as_uint(Bs[(kk + t + 4) * LDA + col]);
            mma_tf32(c[0][ni], a[0], b);
            mma_tf32(c[1][ni], a[1], b);
        }
    }
}

__device__ __forceinline__ void zero_acc8(float c[2][8][4]) {
#pragma unroll
    for (int mi = 0; mi < 2; mi++)
#pragma unroll
        for (int ni = 0; ni < 8; ni++)
#pragma unroll
            for (int j = 0; j < 4; j++) c[mi][ni][j] = 0.f;
}

// Cooperative fills, stride = nthreads
__device__ __forceinline__ void fill_tile_f32(float* __restrict__ dst,
                                              const float* __restrict__ src,
                                              int rows_valid, int tid, int nthreads) {
    for (int i = tid; i < 128 * 32; i += nthreads) {
        int r = i >> 5, c4 = (i & 31) << 2;
        float4 v = make_float4(0.f, 0.f, 0.f, 0.f);
        if (r < rows_valid) v = *(const float4*)(src + (size_t)r * DIM + c4);
        *(float4*)(dst + r * LDA + c4) = v;
    }
}

__device__ __forceinline__ void fill_tile_tf32(float* __restrict__ dst,
                                               const float* __restrict__ src,
                                               int tid, int nthreads) {
    for (int i = tid; i < 128 * 32; i += nthreads) {
        int r = i >> 5, c4 = (i & 31) << 2;
        float4 v = *(const float4*)(src + (size_t)r * DIM + c4);
        v.x = __uint_as_float(f2tf32(v.x));
        v.y = __uint_as_float(f2tf32(v.y));
        v.z = __uint_as_float(f2tf32(v.z));
        v.w = __uint_as_float(f2tf32(v.w));
        *(float4*)(dst + r * LDA + c4) = v;
    }
}

// ---------------------------------------------------------------------------
// Kernel A: P = nfeat @ W1b, Q = nfeat @ W1c   (unchanged, small)
// ---------------------------------------------------------------------------
__global__ void __launch_bounds__(NT_PRE, 1)
precompute_pq(const float* __restrict__ nfeat, const float* __restrict__ W1, int N) {
    extern __shared__ float sm[];
    float* As = sm;
    float* Bs = sm + 128 * LDA;

    int tid = threadIdx.x;
    int lane = tid & 31, w = tid >> 5;
    int wm = w & 3, wn = w >> 2, g = lane >> 2, t = lane & 3;
    int n0 = blockIdx.x * TILE;
    int valid = min(TILE, N - n0);

    fill_tile_f32(As, nfeat + (size_t)n0 * DIM, valid, tid, NT_PRE);
    fill_tile_tf32(Bs, W1 + 128 * DIM, tid, NT_PRE);  // W1b
    __syncthreads();

    float c[2][8][4];
    zero_acc8(c);
    gemm128_pre(As, Bs, c, wm, wn, g, t);

    float* P = g_P + (size_t)n0 * DIM;
#pragma unroll
    for (int mi = 0; mi < 2; mi++)
#pragma unroll
        for (int h = 0; h < 2; h++) {
            int r = wm * 32 + mi * 16 + g + h * 8;
#pragma unroll
            for (int ni = 0; ni < 8; ni++) {
                int col = wn * 64 + ni * 8 + 2 * t;
                *(float2*)(P + (size_t)r * DIM + col) =
                    make_float2(c[mi][ni][h * 2], c[mi][ni][h * 2 + 1]);
            }
        }

    __syncthreads();
    fill_tile_tf32(Bs, W1 + 256 * DIM, tid, NT_PRE);   // W1c
    __syncthreads();

    zero_acc8(c);
    gemm128_pre(As, Bs, c, wm, wn, g, t);

    float* Q = g_Q + (size_t)n0 * DIM;
#pragma unroll
    for (int mi = 0; mi < 2; mi++)
#pragma unroll
        for (int h = 0; h < 2; h++) {
            int r = wm * 32 + mi * 16 + g + h * 8;
#pragma unroll
            for (int ni = 0; ni < 8; ni++) {
                int col = wn * 64 + ni * 8 + 2 * t;
                *(float2*)(Q + (size_t)r * DIM + col) =
                    make_float2(c[mi][ni][h * 2], c[mi][ni][h * 2 + 1]);
            }
        }
}

// ---------------------------------------------------------------------------
// Kernel B: per-edge fused MLP, 512 threads / 16 warps, 32x32 warp tiles
// ---------------------------------------------------------------------------
__global__ void __launch_bounds__(NT_EDGE, 1)
edge_mlp(const float* __restrict__ efeat, const float* __restrict__ W1,
         const float* __restrict__ b1, const float* __restrict__ W2,
         const float* __restrict__ b2, const float* __restrict__ lng,
         const float* __restrict__ lnb, const int* __restrict__ src_idx,
         const int* __restrict__ dst_idx, float* __restrict__ out, int E, int N) {
    extern __shared__ float sm[];
    float* As = sm;                       // efeat tile (raw fp32, kept for residual)
    float* Bs = sm + 128 * LDA;           // W1a then W2 (tf32 bits)
    float* Hs = sm + 2 * 128 * LDA;       // PQ staging, then h (tf32 bits)
    int*   s_src = (int*)(sm + 3 * 128 * LDA);  // 512 B
    int*   s_dst = s_src + 128;                 // 512 B
    float* s_b1  = (float*)(s_dst + 128);       // 512 B
    float* s_b2  = s_b1 + 128;                  // 512 B
    float* s_lng = s_b2 + 128;                  // 512 B
    float* s_lnb = s_lng + 128;                 // 512 B
    float* s_sum = s_lnb + 128;                 // [4][128] -> 2048 B
    float* s_ssq = s_sum + 512;                 // [4][128] -> 2048 B

    int tid = threadIdx.x;
    int lane = tid & 31, w = tid >> 5;
    int wm = w & 3, wn = w >> 2, g = lane >> 2, t = lane & 3;
    int e0 = blockIdx.x * TILE;
    int valid = min(TILE, E - e0);

    if (tid < 128) {
        int e = e0 + tid;
        int si = (tid < valid) ? src_idx[e] : 0;
        int di = (tid < valid) ? dst_idx[e] : 0;
        s_src[tid] = (si >= 0 && si < N) ? si : 0;
        s_dst[tid] = (di >= 0 && di < N) ? di : 0;
        s_b1[tid]  = b1[tid];
        s_b2[tid]  = b2[tid];
        s_lng[tid] = lng[tid];
        s_lnb[tid] = lnb[tid];
    }
    fill_tile_f32(As, efeat + (size_t)e0 * DIM, valid, tid, NT_EDGE);
    fill_tile_tf32(Bs, W1, tid, NT_EDGE);     // W1a
    __syncthreads();

    // Stage PQ[r][c] = P[src[r]][c] + Q[dst[r]][c] + b1[c] into Hs (raw fp32).
    for (int i = tid; i < 128 * 32; i += NT_EDGE) {
        int r = i >> 5, c4 = (i & 31) << 2;
        float4 p = *(const float4*)(g_P + (size_t)s_src[r] * DIM + c4);
        float4 q = *(const float4*)(g_Q + (size_t)s_dst[r] * DIM + c4);
        float4 bb = *(const float4*)(s_b1 + c4);
        float4 v;
        v.x = p.x + q.x + bb.x;
        v.y = p.y + q.y + bb.y;
        v.z = p.z + q.z + bb.z;
        v.w = p.w + q.w + bb.w;
        *(float4*)(Hs + r * LDA + c4) = v;
    }
    __syncthreads();

    float c[2][4][4];
    zero_acc4(c);
    gemm_tile<true>(As, Bs, c, wm, wn, g, t);   // GEMM1 edge part (A=fp32, cvt)

    // silu(frag + PQ) -> overwrite Hs at SAME (r,c) owned by this thread,
    // stored pre-converted to tf32 bits so GEMM2 skips the cvt.
#pragma unroll
    for (int mi = 0; mi < 2; mi++)
#pragma unroll
        for (int ni = 0; ni < 4; ni++)
#pragma unroll
            for (int h = 0; h < 2; h++) {
                int r = wm * 32 + mi * 16 + g + h * 8;
                int col = wn * 32 + ni * 8 + 2 * t;
                float2 pq = *(float2*)(Hs + r * LDA + col);
                float x0 = c[mi][ni][h * 2] + pq.x;
                float x1 = c[mi][ni][h * 2 + 1] + pq.y;
                float s0 = x0 / (1.f + __expf(-x0));
                float s1 = x1 / (1.f + __expf(-x1));
                *(float2*)(Hs + r * LDA + col) =
                    make_float2(__uint_as_float(f2tf32(s0)), __uint_as_float(f2tf32(s1)));
            }
    __syncthreads();
    fill_tile_tf32(Bs, W2, tid, NT_EDGE);
    __syncthreads();

    zero_acc4(c);
    gemm_tile<false>(Hs, Bs, c, wm, wn, g, t);  // GEMM2 (A already tf32 bits)

    // + b2, LayerNorm row stats (4 wn slices)
    float psum[2][2] = {{0.f, 0.f}, {0.f, 0.f}};
    float pssq[2][2] = {{0.f, 0.f}, {0.f, 0.f}};
#pragma unroll
    for (int mi = 0; mi < 2; mi++)
#pragma unroll
        for (int ni = 0; ni < 4; ni++)
#pragma unroll
            for (int j = 0; j < 4; j++) {
                int col = wn * 32 + ni * 8 + 2 * t + (j & 1);
                float v = c[mi][ni][j] + s_b2[col];
                c[mi][ni][j] = v;
                psum[mi][j >> 1] += v;
                pssq[mi][j >> 1] += v * v;
            }
#pragma unroll
    for (int mi = 0; mi < 2; mi++)
#pragma unroll
        for (int h = 0; h < 2; h++) {
            float s = psum[mi][h], q = pssq[mi][h];
            s += __shfl_xor_sync(0xffffffffu, s, 1);
            s += __shfl_xor_sync(0xffffffffu, s, 2);
            q += __shfl_xor_sync(0xffffffffu, q, 1);
            q += __shfl_xor_sync(0xffffffffu, q, 2);
            if (t == 0) {
                int r = wm * 32 + mi * 16 + g + h * 8;
                s_sum[wn * 128 + r] = s;
                s_ssq[wn * 128 + r] = q;
            }
        }
    __syncthreads();

#pragma unroll
    for (int mi = 0; mi < 2; mi++)
#pragma unroll
        for (int h = 0; h < 2; h++) {
            int r = wm * 32 + mi * 16 + g + h * 8;
            float sum = s_sum[r] + s_sum[128 + r] + s_sum[256 + r] + s_sum[384 + r];
            float ssq = s_ssq[r] + s_ssq[128 + r] + s_ssq[256 + r] + s_ssq[384 + r];
            float mean = sum * (1.f / 128.f);
            float var = ssq * (1.f / 128.f) - mean * mean;
            float rstd = rsqrtf(var + 1e-5f);
            if (r < valid) {
#pragma unroll
                for (int ni = 0; ni < 4; ni++) {
                    int col = wn * 32 + ni * 8 + 2 * t;
                    float2 ef = *(float2*)(As + r * LDA + col);
                    float y0 = (c[mi][ni][h * 2] - mean) * rstd * s_lng[col] +
                               s_lnb[col] + ef.x;
                    float y1 = (c[mi][ni][h * 2 + 1] - mean) * rstd * s_lng[col + 1] +
                               s_lnb[col + 1] + ef.y;
                    *(float2*)(out + (size_t)(e0 + r) * DIM + col) = make_float2(y0, y1);
                }
            }
        }
}

// ---------------------------------------------------------------------------
// Launch: size-based input identification (robust to metadata ordering)
// ---------------------------------------------------------------------------
extern "C" void kernel_launch(void* const* d_in, const int* in_sizes, int n_in,
                              void* d_out, int out_size) {
    long long maxsz = 0;
    for (int i = 0; i < n_in; i++)
        if ((long long)in_sizes[i] > maxsz) maxsz = in_sizes[i];
    long long E = maxsz / DIM;

    int i_efeat = -1, i_nfeat = -1, i_W1 = -1, i_W2 = -1;
    int idxArr[2] = {-1, -1};  int nIdx = 0;
    int vecArr[4] = {-1, -1, -1, -1}; int nVec = 0;
    for (int i = 0; i < n_in; i++) {
        long long s = in_sizes[i];
        if (s == maxsz)              i_efeat = i;
        else if (s == 3 * 128 * 128) i_W1 = i;
        else if (s == 128 * 128)     i_W2 = i;
        else if (s == 128)           { if (nVec < 4) vecArr[nVec++] = i; }
        else if (s == E)             { if (nIdx < 2) idxArr[nIdx++] = i; }
        else                         i_nfeat = i;
    }
    bool alpha = (i_W1 == 0);
    int i_src = alpha ? idxArr[1] : idxArr[0];
    int i_dst = alpha ? idxArr[0] : idxArr[1];
    int i_b1 = vecArr[0], i_b2 = vecArr[1];
    int i_lng = alpha ? vecArr[3] : vecArr[2];
    int i_lnb = alpha ? vecArr[2] : vecArr[3];

    const float* efeat = (const float*)d_in[i_efeat];
    const float* nfeat = (const float*)d_in[i_nfeat];
    const int* src_idx = (const int*)d_in[i_src];
    const int* dst_idx = (const int*)d_in[i_dst];
    const float* W1 = (const float*)d_in[i_W1];
    const float* b1 = (const float*)d_in[i_b1];
    const float* W2 = (const float*)d_in[i_W2];
    const float* b2 = (const float*)d_in[i_b2];
    const float* lng = (const float*)d_in[i_lng];
    const float* lnb = (const float*)d_in[i_lnb];
    float* out = (float*)d_out;

    int Ei = (int)E;
    int N = in_sizes[i_nfeat] / DIM;

    const int SMEM_A = 2 * 128 * LDA * (int)sizeof(float);        // 135168 B
    // Tail: src/dst 1024 + 4 vecs 2048 + sum/ssq 4096 = 7168 B
    const int SMEM_B = 3 * 128 * LDA * (int)sizeof(float) + 7168; // 209920 B

    cudaFuncSetAttribute(precompute_pq, cudaFuncAttributeMaxDynamicSharedMemorySize, SMEM_A);
    cudaFuncSetAttribute(edge_mlp, cudaFuncAttributeMaxDynamicSharedMemorySize, SMEM_B);

    int nBlocks = (N + TILE - 1) / TILE;
    if ((long long)nBlocks * TILE > N_PAD_ROWS) nBlocks = N_PAD_ROWS / TILE;

    precompute_pq<<<nBlocks, NT_PRE, SMEM_A>>>(nfeat, W1, N);
    edge_mlp<<<(Ei + TILE - 1) / TILE, NT_EDGE, SMEM_B>>>(
        efeat, W1, b1, W2, b2, lng, lnb, src_idx, dst_idx, out, Ei, N);

    long long need = E * DIM + (long long)N * DIM;
    if ((long long)out_size >= need) {
        cudaMemcpyAsync(out + (size_t)E * DIM, nfeat,
                        (size_t)N * DIM * sizeof(float), cudaMemcpyDeviceToDevice);
    }
}

// round 11
// speedup vs baseline: 1.4516x; 1.0553x over previous
#include <cuda_runtime.h>
#include <cstdint>

// Problem constants: E=1e6, N=1e5, D=128, H=128, CIN=384.
#define DIM       128
#define TILE      128
#define LDA       132      // pitch: conflict-free A-frag loads, float4-aligned
#define NT_PRE    256
#define NT_EDGE   1024

#define N_PAD_ROWS 100096  // 782 * 128

__device__ float g_P[(size_t)N_PAD_ROWS * DIM];
__device__ float g_Q[(size_t)N_PAD_ROWS * DIM];

// ---------------------------------------------------------------------------
__device__ __forceinline__ uint32_t f2tf32(float x) {
    uint32_t u;
    asm("cvt.rna.tf32.f32 %0, %1;" : "=r"(u) : "f"(x));
    return u;
}

__device__ __forceinline__ void mma_tf32(float* c, const uint32_t* a, const uint32_t* b) {
    asm volatile(
        "mma.sync.aligned.m16n8k8.row.col.f32.tf32.tf32.f32 "
        "{%0,%1,%2,%3}, {%4,%5,%6,%7}, {%8,%9}, {%0,%1,%2,%3};\n"
        : "+f"(c[0]), "+f"(c[1]), "+f"(c[2]), "+f"(c[3])
        : "r"(a[0]), "r"(a[1]), "r"(a[2]), "r"(a[3]), "r"(b[0]), "r"(b[1]));
}

// ---------------------------------------------------------------------------
// 16x32 warp-tile GEMM over K=128 from smem (32-warp edge kernel).
// Warp (wm,wn): rows [wm*16,+16), cols [wn*32,+32).
// c[ni][j]: row = wm*16 + g + (j>=2?8:0), col = wn*32 + ni*8 + 2t + (j&1).
template <bool CVT_A>
__device__ __forceinline__ void gemm_tile16(const float* __restrict__ As,
                                            const float* __restrict__ Bs,
                                            float c[4][4], int wm, int wn, int g, int t) {
#pragma unroll
    for (int kk = 0; kk < 128; kk += 8) {
        uint32_t a[4];
        {
            const float* p0 = As + (wm * 16 + g) * LDA + kk + t;
            const float* p1 = As + (wm * 16 + g + 8) * LDA + kk + t;
            if (CVT_A) {
                a[0] = f2tf32(p0[0]);
                a[1] = f2tf32(p1[0]);
                a[2] = f2tf32(p0[4]);
                a[3] = f2tf32(p1[4]);
            } else {
                a[0] = __float_as_uint(p0[0]);
                a[1] = __float_as_uint(p1[0]);
                a[2] = __float_as_uint(p0[4]);
                a[3] = __float_as_uint(p1[4]);
            }
        }
#pragma unroll
        for (int ni = 0; ni < 4; ni++) {
            uint32_t b[2];
            int col = wn * 32 + ni * 8 + g;
            b[0] = __float_as_uint(Bs[(kk + t) * LDA + col]);
            b[1] = __float_as_uint(Bs[(kk + t + 4) * LDA + col]);
            mma_tf32(c[ni], a, b);
        }
    }
}

// 64-wide warp-tile version for precompute (8 warps, 32x64 tiles)
__device__ __forceinline__ void gemm128_pre(const float* __restrict__ As,
                                            const float* __restrict__ Bs,
                                            float c[2][8][4], int wm, int wn, int g, int t) {
#pragma unroll
    for (int kk = 0; kk < 128; kk += 8) {
        uint32_t a[2][4];
#pragma unroll
        for (int mi = 0; mi < 2; mi++) {
            int r0 = wm * 32 + mi * 16;
            a[mi][0] = f2tf32(As[(r0 + g) * LDA + kk + t]);
            a[mi][1] = f2tf32(As[(r0 + g + 8) * LDA + kk + t]);
            a[mi][2] = f2tf32(As[(r0 + g) * LDA + kk + t + 4]);
            a[mi][3] = f2tf32(As[(r0 + g + 8) * LDA + kk + t + 4]);
        }
#pragma unroll
        for (int ni = 0; ni < 8; ni++) {
            uint32_t b[2];
            int col = wn * 64 + ni * 8 + g;
            b[0] = __float_as_uint(Bs[(kk + t) * LDA + col]);
            b[1] = __float_as_uint(Bs[(kk + t + 4) * LDA + col]);
            mma_tf32(c[0][ni], a[0], b);
            mma_tf32(c[1][ni], a[1], b);
        }
    }
}

// Cooperative fills, stride = nthreads
__device__ __forceinline__ void fill_tile_f32(float* __restrict__ dst,
                                              const float* __restrict__ src,
                                              int rows_valid, int tid, int nthreads) {
    for (int i = tid; i < 128 * 32; i += nthreads) {
        int r = i >> 5, c4 = (i & 31) << 2;
        float4 v = make_float4(0.f, 0.f, 0.f, 0.f);
        if (r < rows_valid) v = *(const float4*)(src + (size_t)r * DIM + c4);
        *(float4*)(dst + r * LDA + c4) = v;
    }
}

__device__ __forceinline__ void fill_tile_tf32(float* __restrict__ dst,
                                               const float* __restrict__ src,
                                               int tid, int nthreads) {
    for (int i = tid; i < 128 * 32; i += nthreads) {
        int r = i >> 5, c4 = (i & 31) << 2;
        float4 v = *(const float4*)(src + (size_t)r * DIM + c4);
        v.x = __uint_as_float(f2tf32(v.x));
        v.y = __uint_as_float(f2tf32(v.y));
        v.z = __uint_as_float(f2tf32(v.z));
        v.w = __uint_as_float(f2tf32(v.w));
        *(float4*)(dst + r * LDA + c4) = v;
    }
}

// ---------------------------------------------------------------------------
// Kernel A: P = nfeat @ W1b, Q = nfeat @ W1c   (unchanged, small)
// ---------------------------------------------------------------------------
__global__ void __launch_bounds__(NT_PRE, 1)
precompute_pq(const float* __restrict__ nfeat, const float* __restrict__ W1, int N) {
    extern __shared__ float sm[];
    float* As = sm;
    float* Bs = sm + 128 * LDA;

    int tid = threadIdx.x;
    int lane = tid & 31, w = tid >> 5;
    int wm = w & 3, wn = w >> 2, g = lane >> 2, t = lane & 3;
    int n0 = blockIdx.x * TILE;
    int valid = min(TILE, N - n0);

    fill_tile_f32(As, nfeat + (size_t)n0 * DIM, valid, tid, NT_PRE);
    fill_tile_tf32(Bs, W1 + 128 * DIM, tid, NT_PRE);  // W1b
    __syncthreads();

    float c[2][8][4];
#pragma unroll
    for (int mi = 0; mi < 2; mi++)
#pragma unroll
        for (int ni = 0; ni < 8; ni++)
#pragma unroll
            for (int j = 0; j < 4; j++) c[mi][ni][j] = 0.f;
    gemm128_pre(As, Bs, c, wm, wn, g, t);

    float* P = g_P + (size_t)n0 * DIM;
#pragma unroll
    for (int mi = 0; mi < 2; mi++)
#pragma unroll
        for (int h = 0; h < 2; h++) {
            int r = wm * 32 + mi * 16 + g + h * 8;
#pragma unroll
            for (int ni = 0; ni < 8; ni++) {
                int col = wn * 64 + ni * 8 + 2 * t;
                *(float2*)(P + (size_t)r * DIM + col) =
                    make_float2(c[mi][ni][h * 2], c[mi][ni][h * 2 + 1]);
            }
        }

    __syncthreads();
    fill_tile_tf32(Bs, W1 + 256 * DIM, tid, NT_PRE);   // W1c
    __syncthreads();

#pragma unroll
    for (int mi = 0; mi < 2; mi++)
#pragma unroll
        for (int ni = 0; ni < 8; ni++)
#pragma unroll
            for (int j = 0; j < 4; j++) c[mi][ni][j] = 0.f;
    gemm128_pre(As, Bs, c, wm, wn, g, t);

    float* Q = g_Q + (size_t)n0 * DIM;
#pragma unroll
    for (int mi = 0; mi < 2; mi++)
#pragma unroll
        for (int h = 0; h < 2; h++) {
            int r = wm * 32 + mi * 16 + g + h * 8;
#pragma unroll
            for (int ni = 0; ni < 8; ni++) {
                int col = wn * 64 + ni * 8 + 2 * t;
                *(float2*)(Q + (size_t)r * DIM + col) =
                    make_float2(c[mi][ni][h * 2], c[mi][ni][h * 2 + 1]);
            }
        }
}

// ---------------------------------------------------------------------------
// Kernel B: per-edge fused MLP, 1024 threads / 32 warps, 16x32 warp tiles.
// ---------------------------------------------------------------------------
__global__ void __launch_bounds__(NT_EDGE, 1)
edge_mlp(const float* __restrict__ efeat, const float* __restrict__ W1,
         const float* __restrict__ b1, const float* __restrict__ W2,
         const float* __restrict__ b2, const float* __restrict__ lng,
         const float* __restrict__ lnb, const int* __restrict__ src_idx,
         const int* __restrict__ dst_idx, float* __restrict__ out, int E, int N) {
    extern __shared__ float sm[];
    float* As = sm;                       // efeat tile (raw fp32, kept for residual)
    float* Bs = sm + 128 * LDA;           // W1a then W2 (tf32 bits)
    float* Hs = sm + 2 * 128 * LDA;       // PQ staging, then h (tf32 bits)
    int*   s_src = (int*)(sm + 3 * 128 * LDA);  // 512 B
    int*   s_dst = s_src + 128;                 // 512 B
    float* s_b1  = (float*)(s_dst + 128);       // 512 B
    float* s_b2  = s_b1 + 128;                  // 512 B
    float* s_lng = s_b2 + 128;                  // 512 B
    float* s_lnb = s_lng + 128;                 // 512 B
    float* s_sum = s_lnb + 128;                 // [4][128] -> 2048 B
    float* s_ssq = s_sum + 512;                 // [4][128] -> 2048 B

    int tid = threadIdx.x;
    int lane = tid & 31, w = tid >> 5;
    int wm = w & 7, wn = w >> 3, g = lane >> 2, t = lane & 3;
    int e0 = blockIdx.x * TILE;
    int valid = min(TILE, E - e0);

    if (tid < 128) {
        int e = e0 + tid;
        int si = (tid < valid) ? src_idx[e] : 0;
        int di = (tid < valid) ? dst_idx[e] : 0;
        s_src[tid] = (si >= 0 && si < N) ? si : 0;
        s_dst[tid] = (di >= 0 && di < N) ? di : 0;
        s_b1[tid]  = b1[tid];
        s_b2[tid]  = b2[tid];
        s_lng[tid] = lng[tid];
        s_lnb[tid] = lnb[tid];
    }
    fill_tile_f32(As, efeat + (size_t)e0 * DIM, valid, tid, NT_EDGE);
    fill_tile_tf32(Bs, W1, tid, NT_EDGE);     // W1a
    __syncthreads();

    // Stage PQ[r][c] = P[src[r]][c] + Q[dst[r]][c] + b1[c] into Hs (raw fp32).
    for (int i = tid; i < 128 * 32; i += NT_EDGE) {
        int r = i >> 5, c4 = (i & 31) << 2;
        float4 p = *(const float4*)(g_P + (size_t)s_src[r] * DIM + c4);
        float4 q = *(const float4*)(g_Q + (size_t)s_dst[r] * DIM + c4);
        float4 bb = *(const float4*)(s_b1 + c4);
        float4 v;
        v.x = p.x + q.x + bb.x;
        v.y = p.y + q.y + bb.y;
        v.z = p.z + q.z + bb.z;
        v.w = p.w + q.w + bb.w;
        *(float4*)(Hs + r * LDA + c4) = v;
    }
    __syncthreads();

    float c[4][4];
#pragma unroll
    for (int ni = 0; ni < 4; ni++)
#pragma unroll
        for (int j = 0; j < 4; j++) c[ni][j] = 0.f;
    gemm_tile16<true>(As, Bs, c, wm, wn, g, t);   // GEMM1 edge part

    // silu(frag + PQ) -> overwrite Hs at SAME (r,c) this thread owns,
    // pre-converted to tf32 bits so GEMM2 skips the cvt.
#pragma unroll
    for (int ni = 0; ni < 4; ni++)
#pragma unroll
        for (int h = 0; h < 2; h++) {
            int r = wm * 16 + g + h * 8;
            int col = wn * 32 + ni * 8 + 2 * t;
            float2 pq = *(float2*)(Hs + r * LDA + col);
            float x0 = c[ni][h * 2] + pq.x;
            float x1 = c[ni][h * 2 + 1] + pq.y;
            float s0 = x0 / (1.f + __expf(-x0));
            float s1 = x1 / (1.f + __expf(-x1));
            *(float2*)(Hs + r * LDA + col) =
                make_float2(__uint_as_float(f2tf32(s0)), __uint_as_float(f2tf32(s1)));
        }
    __syncthreads();
    fill_tile_tf32(Bs, W2, tid, NT_EDGE);
    __syncthreads();

#pragma unroll
    for (int ni = 0; ni < 4; ni++)
#pragma unroll
        for (int j = 0; j < 4; j++) c[ni][j] = 0.f;
    gemm_tile16<false>(Hs, Bs, c, wm, wn, g, t);  // GEMM2 (A already tf32 bits)

    // + b2, LayerNorm row stats (4 wn slices)
    float psum[2] = {0.f, 0.f};
    float pssq[2] = {0.f, 0.f};
#pragma unroll
    for (int ni = 0; ni < 4; ni++)
#pragma unroll
        for (int j = 0; j < 4; j++) {
            int col = wn * 32 + ni * 8 + 2 * t + (j & 1);
            float v = c[ni][j] + s_b2[col];
            c[ni][j] = v;
            psum[j >> 1] += v;
            pssq[j >> 1] += v * v;
        }
#pragma unroll
    for (int h = 0; h < 2; h++) {
        float s = psum[h], q = pssq[h];
        s += __shfl_xor_sync(0xffffffffu, s, 1);
        s += __shfl_xor_sync(0xffffffffu, s, 2);
        q += __shfl_xor_sync(0xffffffffu, q, 1);
        q += __shfl_xor_sync(0xffffffffu, q, 2);
        if (t == 0) {
            int r = wm * 16 + g + h * 8;
            s_sum[wn * 128 + r] = s;
            s_ssq[wn * 128 + r] = q;
        }
    }
    __syncthreads();

#pragma unroll
    for (int h = 0; h < 2; h++) {
        int r = wm * 16 + g + h * 8;
        float sum = s_sum[r] + s_sum[128 + r] + s_sum[256 + r] + s_sum[384 + r];
        float ssq = s_ssq[r] + s_ssq[128 + r] + s_ssq[256 + r] + s_ssq[384 + r];
        float mean = sum * (1.f / 128.f);
        float var = ssq * (1.f / 128.f) - mean * mean;
        float rstd = rsqrtf(var + 1e-5f);
        if (r < valid) {
#pragma unroll
            for (int ni = 0; ni < 4; ni++) {
                int col = wn * 32 + ni * 8 + 2 * t;
                float2 ef = *(float2*)(As + r * LDA + col);
                float y0 = (c[ni][h * 2] - mean) * rstd * s_lng[col] +
                           s_lnb[col] + ef.x;
                float y1 = (c[ni][h * 2 + 1] - mean) * rstd * s_lng[col + 1] +
                           s_lnb[col + 1] + ef.y;
                *(float2*)(out + (size_t)(e0 + r) * DIM + col) = make_float2(y0, y1);
            }
        }
    }
}

// ---------------------------------------------------------------------------
// Launch: size-based input identification (robust to metadata ordering)
// ---------------------------------------------------------------------------
extern "C" void kernel_launch(void* const* d_in, const int* in_sizes, int n_in,
                              void* d_out, int out_size) {
    long long maxsz = 0;
    for (int i = 0; i < n_in; i++)
        if ((long long)in_sizes[i] > maxsz) maxsz = in_sizes[i];
    long long E = maxsz / DIM;

    int i_efeat = -1, i_nfeat = -1, i_W1 = -1, i_W2 = -1;
    int idxArr[2] = {-1, -1};  int nIdx = 0;
    int vecArr[4] = {-1, -1, -1, -1}; int nVec = 0;
    for (int i = 0; i < n_in; i++) {
        long long s = in_sizes[i];
        if (s == maxsz)              i_efeat = i;
        else if (s == 3 * 128 * 128) i_W1 = i;
        else if (s == 128 * 128)     i_W2 = i;
        else if (s == 128)           { if (nVec < 4) vecArr[nVec++] = i; }
        else if (s == E)             { if (nIdx < 2) idxArr[nIdx++] = i; }
        else                         i_nfeat = i;
    }
    bool alpha = (i_W1 == 0);
    int i_src = alpha ? idxArr[1] : idxArr[0];
    int i_dst = alpha ? idxArr[0] : idxArr[1];
    int i_b1 = vecArr[0], i_b2 = vecArr[1];
    int i_lng = alpha ? vecArr[3] : vecArr[2];
    int i_lnb = alpha ? vecArr[2] : vecArr[3];

    const float* efeat = (const float*)d_in[i_efeat];
    const float* nfeat = (const float*)d_in[i_nfeat];
    const int* src_idx = (const int*)d_in[i_src];
    const int* dst_idx = (const int*)d_in[i_dst];
    const float* W1 = (const float*)d_in[i_W1];
    const float* b1 = (const float*)d_in[i_b1];
    const float* W2 = (const float*)d_in[i_W2];
    const float* b2 = (const float*)d_in[i_b2];
    const float* lng = (const float*)d_in[i_lng];
    const float* lnb = (const float*)d_in[i_lnb];
    float* out = (float*)d_out;

    int Ei = (int)E;
    int N = in_sizes[i_nfeat] / DIM;

    const int SMEM_A = 2 * 128 * LDA * (int)sizeof(float);        // 135168 B
    // Tail: src/dst 1024 + 4 vecs 2048 + sum/ssq 4096 = 7168 B
    const int SMEM_B = 3 * 128 * LDA * (int)sizeof(float) + 7168; // 209920 B

    cudaFuncSetAttribute(precompute_pq, cudaFuncAttributeMaxDynamicSharedMemorySize, SMEM_A);
    cudaFuncSetAttribute(edge_mlp, cudaFuncAttributeMaxDynamicSharedMemorySize, SMEM_B);

    int nBlocks = (N + TILE - 1) / TILE;
    if ((long long)nBlocks * TILE > N_PAD_ROWS) nBlocks = N_PAD_ROWS / TILE;

    precompute_pq<<<nBlocks, NT_PRE, SMEM_A>>>(nfeat, W1, N);
    edge_mlp<<<(Ei + TILE - 1) / TILE, NT_EDGE, SMEM_B>>>(
        efeat, W1, b1, W2, b2, lng, lnb, src_idx, dst_idx, out, Ei, N);

    long long need = E * DIM + (long long)N * DIM;
    if ((long long)out_size >= need) {
        cudaMemcpyAsync(out + (size_t)E * DIM, nfeat,
                        (size_t)N * DIM * sizeof(float), cudaMemcpyDeviceToDevice);
    }
}

// round 13
// speedup vs baseline: 1.6621x; 1.1450x over previous
#include <cuda_runtime.h>
#include <cstdint>

// Problem constants: E=1e6, N=1e5, D=128, H=128, CIN=384.
#define DIM       128
#define TILE      128
#define LDA       132      // pitch for A/H tiles: A-frag bank = 4g+t, conflict-free
#define LDB       136      // pitch for W tiles:   B-frag bank = 8t+g, conflict-free
#define NT_PRE    256
#define NT_EDGE   1024

#define N_PAD_ROWS 100096  // 782 * 128

__device__ float g_P[(size_t)N_PAD_ROWS * DIM];
__device__ float g_Q[(size_t)N_PAD_ROWS * DIM];

// ---------------------------------------------------------------------------
__device__ __forceinline__ uint32_t f2tf32(float x) {
    uint32_t u;
    asm("cvt.rna.tf32.f32 %0, %1;" : "=r"(u) : "f"(x));
    return u;
}

__device__ __forceinline__ void mma_tf32(float* c, const uint32_t* a, const uint32_t* b) {
    asm volatile(
        "mma.sync.aligned.m16n8k8.row.col.f32.tf32.tf32.f32 "
        "{%0,%1,%2,%3}, {%4,%5,%6,%7}, {%8,%9}, {%0,%1,%2,%3};\n"
        : "+f"(c[0]), "+f"(c[1]), "+f"(c[2]), "+f"(c[3])
        : "r"(a[0]), "r"(a[1]), "r"(a[2]), "r"(a[3]), "r"(b[0]), "r"(b[1]));
}

// ---------------------------------------------------------------------------
// 16x32 warp-tile GEMM over K=128. A from pitch-LDA smem, B from pitch-LDB smem.
// Warp (wm,wn): rows [wm*16,+16), cols [wn*32,+32).
// c[ni][j]: row = wm*16 + g + (j>=2?8:0), col = wn*32 + ni*8 + 2t + (j&1).
template <bool CVT_A>
__device__ __forceinline__ void gemm_tile16(const float* __restrict__ As,
                                            const float* __restrict__ Bs,
                                            float c[4][4], int wm, int wn, int g, int t) {
#pragma unroll
    for (int kk = 0; kk < 128; kk += 8) {
        uint32_t a[4];
        {
            const float* p0 = As + (wm * 16 + g) * LDA + kk + t;
            const float* p1 = As + (wm * 16 + g + 8) * LDA + kk + t;
            if (CVT_A) {
                a[0] = f2tf32(p0[0]);
                a[1] = f2tf32(p1[0]);
                a[2] = f2tf32(p0[4]);
                a[3] = f2tf32(p1[4]);
            } else {
                a[0] = __float_as_uint(p0[0]);
                a[1] = __float_as_uint(p1[0]);
                a[2] = __float_as_uint(p0[4]);
                a[3] = __float_as_uint(p1[4]);
            }
        }
#pragma unroll
        for (int ni = 0; ni < 4; ni++) {
            uint32_t b[2];
            int col = wn * 32 + ni * 8 + g;
            b[0] = __float_as_uint(Bs[(kk + t) * LDB + col]);
            b[1] = __float_as_uint(Bs[(kk + t + 4) * LDB + col]);
            mma_tf32(c[ni], a, b);
        }
    }
}

// 64-wide warp-tile version for precompute (8 warps, 32x64 tiles)
__device__ __forceinline__ void gemm128_pre(const float* __restrict__ As,
                                            const float* __restrict__ Bs,
                                            float c[2][8][4], int wm, int wn, int g, int t) {
#pragma unroll
    for (int kk = 0; kk < 128; kk += 8) {
        uint32_t a[2][4];
#pragma unroll
        for (int mi = 0; mi < 2; mi++) {
            int r0 = wm * 32 + mi * 16;
            a[mi][0] = f2tf32(As[(r0 + g) * LDA + kk + t]);
            a[mi][1] = f2tf32(As[(r0 + g + 8) * LDA + kk + t]);
            a[mi][2] = f2tf32(As[(r0 + g) * LDA + kk + t + 4]);
            a[mi][3] = f2tf32(As[(r0 + g + 8) * LDA + kk + t + 4]);
        }
#pragma unroll
        for (int ni = 0; ni < 8; ni++) {
            uint32_t b[2];
            int col = wn * 64 + ni * 8 + g;
            b[0] = __float_as_uint(Bs[(kk + t) * LDB + col]);
            b[1] = __float_as_uint(Bs[(kk + t + 4) * LDB + col]);
            mma_tf32(c[0][ni], a[0], b);
            mma_tf32(c[1][ni], a[1], b);
        }
    }
}

// Cooperative fills. pitch-parameterized.
__device__ __forceinline__ void fill_tile_f32(float* __restrict__ dst,
                                              const float* __restrict__ src,
                                              int rows_valid, int tid, int nthreads) {
    for (int i = tid; i < 128 * 32; i += nthreads) {
        int r = i >> 5, c4 = (i & 31) << 2;
        float4 v = make_float4(0.f, 0.f, 0.f, 0.f);
        if (r < rows_valid) v = *(const float4*)(src + (size_t)r * DIM + c4);
        *(float4*)(dst + r * LDA + c4) = v;
    }
}

__device__ __forceinline__ void fill_w_tf32(float* __restrict__ dst,
                                            const float* __restrict__ src,
                                            int tid, int nthreads) {
    for (int i = tid; i < 128 * 32; i += nthreads) {
        int r = i >> 5, c4 = (i & 31) << 2;
        float4 v = *(const float4*)(src + (size_t)r * DIM + c4);
        v.x = __uint_as_float(f2tf32(v.x));
        v.y = __uint_as_float(f2tf32(v.y));
        v.z = __uint_as_float(f2tf32(v.z));
        v.w = __uint_as_float(f2tf32(v.w));
        *(float4*)(dst + r * LDB + c4) = v;
    }
}

// ---------------------------------------------------------------------------
// Kernel A: P = nfeat @ W1b, Q = nfeat @ W1c
// ---------------------------------------------------------------------------
__global__ void __launch_bounds__(NT_PRE, 1)
precompute_pq(const float* __restrict__ nfeat, const float* __restrict__ W1, int N) {
    extern __shared__ float sm[];
    float* As = sm;                 // 128 x LDA
    float* Bs = sm + 128 * LDA;     // 128 x LDB

    int tid = threadIdx.x;
    int lane = tid & 31, w = tid >> 5;
    int wm = w & 3, wn = w >> 2, g = lane >> 2, t = lane & 3;
    int n0 = blockIdx.x * TILE;
    int valid = min(TILE, N - n0);

    fill_tile_f32(As, nfeat + (size_t)n0 * DIM, valid, tid, NT_PRE);
    fill_w_tf32(Bs, W1 + 128 * DIM, tid, NT_PRE);  // W1b
    __syncthreads();

    float c[2][8][4];
#pragma unroll
    for (int mi = 0; mi < 2; mi++)
#pragma unroll
        for (int ni = 0; ni < 8; ni++)
#pragma unroll
            for (int j = 0; j < 4; j++) c[mi][ni][j] = 0.f;
    gemm128_pre(As, Bs, c, wm, wn, g, t);

    float* P = g_P + (size_t)n0 * DIM;
#pragma unroll
    for (int mi = 0; mi < 2; mi++)
#pragma unroll
        for (int h = 0; h < 2; h++) {
            int r = wm * 32 + mi * 16 + g + h * 8;
#pragma unroll
            for (int ni = 0; ni < 8; ni++) {
                int col = wn * 64 + ni * 8 + 2 * t;
                *(float2*)(P + (size_t)r * DIM + col) =
                    make_float2(c[mi][ni][h * 2], c[mi][ni][h * 2 + 1]);
            }
        }

    __syncthreads();
    fill_w_tf32(Bs, W1 + 256 * DIM, tid, NT_PRE);   // W1c
    __syncthreads();

#pragma unroll
    for (int mi = 0; mi < 2; mi++)
#pragma unroll
        for (int ni = 0; ni < 8; ni++)
#pragma unroll
            for (int j = 0; j < 4; j++) c[mi][ni][j] = 0.f;
    gemm128_pre(As, Bs, c, wm, wn, g, t);

    float* Q = g_Q + (size_t)n0 * DIM;
#pragma unroll
    for (int mi = 0; mi < 2; mi++)
#pragma unroll
        for (int h = 0; h < 2; h++) {
            int r = wm * 32 + mi * 16 + g + h * 8;
#pragma unroll
            for (int ni = 0; ni < 8; ni++) {
                int col = wn * 64 + ni * 8 + 2 * t;
                *(float2*)(Q + (size_t)r * DIM + col) =
                    make_float2(c[mi][ni][h * 2], c[mi][ni][h * 2 + 1]);
            }
        }
}

// ---------------------------------------------------------------------------
// Kernel B: per-edge fused MLP, 1024 threads / 32 warps, 16x32 warp tiles.
// ---------------------------------------------------------------------------
__global__ void __launch_bounds__(NT_EDGE, 1)
edge_mlp(const float* __restrict__ efeat, const float* __restrict__ W1,
         const float* __restrict__ b1, const float* __restrict__ W2,
         const float* __restrict__ b2, const float* __restrict__ lng,
         const float* __restrict__ lnb, const int* __restrict__ src_idx,
         const int* __restrict__ dst_idx, float* __restrict__ out, int E, int N) {
    extern __shared__ float sm[];
    float* As = sm;                             // efeat tile, pitch LDA (raw fp32)
    float* Bs = sm + 128 * LDA;                 // W1a then W2 (tf32 bits), pitch LDB
    float* Hs = Bs + 128 * LDB;                 // PQ staging, then h, pitch LDA
    float* tail = Hs + 128 * LDA;
    int*   s_src = (int*)tail;                  // 512 B
    int*   s_dst = s_src + 128;                 // 512 B
    float* s_b1  = (float*)(s_dst + 128);       // 512 B
    float* s_b2  = s_b1 + 128;                  // 512 B
    float* s_lng = s_b2 + 128;                  // 512 B
    float* s_lnb = s_lng + 128;                 // 512 B
    float* s_sum = s_lnb + 128;                 // [4][128] -> 2048 B
    float* s_ssq = s_sum + 512;                 // [4][128] -> 2048 B

    int tid = threadIdx.x;
    int lane = tid & 31, w = tid >> 5;
    int wm = w & 7, wn = w >> 3, g = lane >> 2, t = lane & 3;
    int e0 = blockIdx.x * TILE;
    int valid = min(TILE, E - e0);

    if (tid < 128) {
        int e = e0 + tid;
        int si = (tid < valid) ? src_idx[e] : 0;
        int di = (tid < valid) ? dst_idx[e] : 0;
        s_src[tid] = (si >= 0 && si < N) ? si : 0;
        s_dst[tid] = (di >= 0 && di < N) ? di : 0;
        s_b1[tid]  = b1[tid];
        s_b2[tid]  = b2[tid];
        s_lng[tid] = lng[tid];
        s_lnb[tid] = lnb[tid];
    }
    fill_tile_f32(As, efeat + (size_t)e0 * DIM, valid, tid, NT_EDGE);
    fill_w_tf32(Bs, W1, tid, NT_EDGE);     // W1a
    __syncthreads();

    // Stage PQ[r][c] = P[src[r]][c] + Q[dst[r]][c] + b1[c] into Hs (raw fp32).
    for (int i = tid; i < 128 * 32; i += NT_EDGE) {
        int r = i >> 5, c4 = (i & 31) << 2;
        float4 p = *(const float4*)(g_P + (size_t)s_src[r] * DIM + c4);
        float4 q = *(const float4*)(g_Q + (size_t)s_dst[r] * DIM + c4);
        float4 bb = *(const float4*)(s_b1 + c4);
        float4 v;
        v.x = p.x + q.x + bb.x;
        v.y = p.y + q.y + bb.y;
        v.z = p.z + q.z + bb.z;
        v.w = p.w + q.w + bb.w;
        *(float4*)(Hs + r * LDA + c4) = v;
    }
    __syncthreads();

    float c[4][4];
#pragma unroll
    for (int ni = 0; ni < 4; ni++)
#pragma unroll
        for (int j = 0; j < 4; j++) c[ni][j] = 0.f;
    gemm_tile16<true>(As, Bs, c, wm, wn, g, t);   // GEMM1 edge part

    // silu(frag + PQ) -> overwrite Hs at SAME (r,c) this thread owns,
    // pre-converted to tf32 bits so GEMM2 skips the cvt.
#pragma unroll
    for (int ni = 0; ni < 4; ni++)
#pragma unroll
        for (int h = 0; h < 2; h++) {
            int r = wm * 16 + g + h * 8;
            int col = wn * 32 + ni * 8 + 2 * t;
            float2 pq = *(float2*)(Hs + r * LDA + col);
            float x0 = c[ni][h * 2] + pq.x;
            float x1 = c[ni][h * 2 + 1] + pq.y;
            float s0 = x0 / (1.f + __expf(-x0));
            float s1 = x1 / (1.f + __expf(-x1));
            *(float2*)(Hs + r * LDA + col) =
                make_float2(__uint_as_float(f2tf32(s0)), __uint_as_float(f2tf32(s1)));
        }
    __syncthreads();
    fill_w_tf32(Bs, W2, tid, NT_EDGE);
    __syncthreads();

#pragma unroll
    for (int ni = 0; ni < 4; ni++)
#pragma unroll
        for (int j = 0; j < 4; j++) c[ni][j] = 0.f;
    gemm_tile16<false>(Hs, Bs, c, wm, wn, g, t);  // GEMM2 (A already tf32 bits)

    // + b2, LayerNorm row stats (4 wn slices)
    float psum[2] = {0.f, 0.f};
    float pssq[2] = {0.f, 0.f};
#pragma unroll
    for (int ni = 0; ni < 4; ni++)
#pragma unroll
        for (int j = 0; j < 4; j++) {
            int col = wn * 32 + ni * 8 + 2 * t + (j & 1);
            float v = c[ni][j] + s_b2[col];
            c[ni][j] = v;
            psum[j >> 1] += v;
            pssq[j >> 1] += v * v;
        }
#pragma unroll
    for (int h = 0; h < 2; h++) {
        float s = psum[h], q = pssq[h];
        s += __shfl_xor_sync(0xffffffffu, s, 1);
        s += __shfl_xor_sync(0xffffffffu, s, 2);
        q += __shfl_xor_sync(0xffffffffu, q, 1);
        q += __shfl_xor_sync(0xffffffffu, q, 2);
        if (t == 0) {
            int r = wm * 16 + g + h * 8;
            s_sum[wn * 128 + r] = s;
            s_ssq[wn * 128 + r] = q;
        }
    }
    __syncthreads();

#pragma unroll
    for (int h = 0; h < 2; h++) {
        int r = wm * 16 + g + h * 8;
        float sum = s_sum[r] + s_sum[128 + r] + s_sum[256 + r] + s_sum[384 + r];
        float ssq = s_ssq[r] + s_ssq[128 + r] + s_ssq[256 + r] + s_ssq[384 + r];
        float mean = sum * (1.f / 128.f);
        float var = ssq * (1.f / 128.f) - mean * mean;
        float rstd = rsqrtf(var + 1e-5f);
        if (r < valid) {
#pragma unroll
            for (int ni = 0; ni < 4; ni++) {
                int col = wn * 32 + ni * 8 + 2 * t;
                float2 ef = *(float2*)(As + r * LDA + col);
                float y0 = (c[ni][h * 2] - mean) * rstd * s_lng[col] +
                           s_lnb[col] + ef.x;
                float y1 = (c[ni][h * 2 + 1] - mean) * rstd * s_lng[col + 1] +
                           s_lnb[col + 1] + ef.y;
                *(float2*)(out + (size_t)(e0 + r) * DIM + col) = make_float2(y0, y1);
            }
        }
    }
}

// ---------------------------------------------------------------------------
// Launch: size-based input identification (robust to metadata ordering)
// ---------------------------------------------------------------------------
extern "C" void kernel_launch(void* const* d_in, const int* in_sizes, int n_in,
                              void* d_out, int out_size) {
    long long maxsz = 0;
    for (int i = 0; i < n_in; i++)
        if ((long long)in_sizes[i] > maxsz) maxsz = in_sizes[i];
    long long E = maxsz / DIM;

    int i_efeat = -1, i_nfeat = -1, i_W1 = -1, i_W2 = -1;
    int idxArr[2] = {-1, -1};  int nIdx = 0;
    int vecArr[4] = {-1, -1, -1, -1}; int nVec = 0;
    for (int i = 0; i < n_in; i++) {
        long long s = in_sizes[i];
        if (s == maxsz)              i_efeat = i;
        else if (s == 3 * 128 * 128) i_W1 = i;
        else if (s == 128 * 128)     i_W2 = i;
        else if (s == 128)           { if (nVec < 4) vecArr[nVec++] = i; }
        else if (s == E)             { if (nIdx < 2) idxArr[nIdx++] = i; }
        else                         i_nfeat = i;
    }
    bool alpha = (i_W1 == 0);
    int i_src = alpha ? idxArr[1] : idxArr[0];
    int i_dst = alpha ? idxArr[0] : idxArr[1];
    int i_b1 = vecArr[0], i_b2 = vecArr[1];
    int i_lng = alpha ? vecArr[3] : vecArr[2];
    int i_lnb = alpha ? vecArr[2] : vecArr[3];

    const float* efeat = (const float*)d_in[i_efeat];
    const float* nfeat = (const float*)d_in[i_nfeat];
    const int* src_idx = (const int*)d_in[i_src];
    const int* dst_idx = (const int*)d_in[i_dst];
    const float* W1 = (const float*)d_in[i_W1];
    const float* b1 = (const float*)d_in[i_b1];
    const float* W2 = (const float*)d_in[i_W2];
    const float* b2 = (const float*)d_in[i_b2];
    const float* lng = (const float*)d_in[i_lng];
    const float* lnb = (const float*)d_in[i_lnb];
    float* out = (float*)d_out;

    int Ei = (int)E;
    int N = in_sizes[i_nfeat] / DIM;

    const int SMEM_A = (128 * LDA + 128 * LDB) * (int)sizeof(float);  // 137216 B
    // As + Bs + Hs + tail(7168 B)
    const int SMEM_B =
        (128 * LDA + 128 * LDB + 128 * LDA) * (int)sizeof(float) + 7168;  // 211968 B

    cudaFuncSetAttribute(precompute_pq, cudaFuncAttributeMaxDynamicSharedMemorySize, SMEM_A);
    cudaFuncSetAttribute(edge_mlp, cudaFuncAttributeMaxDynamicSharedMemorySize, SMEM_B);

    int nBlocks = (N + TILE - 1) / TILE;
    if ((long long)nBlocks * TILE > N_PAD_ROWS) nBlocks = N_PAD_ROWS / TILE;

    precompute_pq<<<nBlocks, NT_PRE, SMEM_A>>>(nfeat, W1, N);
    edge_mlp<<<(Ei + TILE - 1) / TILE, NT_EDGE, SMEM_B>>>(
        efeat, W1, b1, W2, b2, lng, lnb, src_idx, dst_idx, out, Ei, N);

    long long need = E * DIM + (long long)N * DIM;
    if ((long long)out_size >= need) {
        cudaMemcpyAsync(out + (size_t)E * DIM, nfeat,
                        (size_t)N * DIM * sizeof(float), cudaMemcpyDeviceToDevice);
    }
}

// round 15
// speedup vs baseline: 2.0940x; 1.2599x over previous
#include <cuda_runtime.h>
#include <cuda_fp16.h>
#include <cstdint>

// Problem constants: E=1e6, N=1e5, D=128, H=128, CIN=384.
#define DIM       128
#define TILE      128
#define LDA       132      // fp32 pitch (precompute tiles + S buffer)
#define LDB       136      // fp32 pitch (precompute weight tile)
#define LDH       68       // half2 pitch for fp16 tiles (136 halves = 272 B/row)
#define NT_PRE    256
#define NT_EDGE   1024

#define N_PAD_ROWS 100096  // 782 * 128

__device__ float g_P[(size_t)N_PAD_ROWS * DIM];
__device__ float g_Q[(size_t)N_PAD_ROWS * DIM];

// ===========================================================================
// tf32 helpers (precompute kernel — unchanged from R13 passing version)
// ===========================================================================
__device__ __forceinline__ uint32_t f2tf32(float x) {
    uint32_t u;
    asm("cvt.rna.tf32.f32 %0, %1;" : "=r"(u) : "f"(x));
    return u;
}

__device__ __forceinline__ void mma_tf32(float* c, const uint32_t* a, const uint32_t* b) {
    asm volatile(
        "mma.sync.aligned.m16n8k8.row.col.f32.tf32.tf32.f32 "
        "{%0,%1,%2,%3}, {%4,%5,%6,%7}, {%8,%9}, {%0,%1,%2,%3};\n"
        : "+f"(c[0]), "+f"(c[1]), "+f"(c[2]), "+f"(c[3])
        : "r"(a[0]), "r"(a[1]), "r"(a[2]), "r"(a[3]), "r"(b[0]), "r"(b[1]));
}

__device__ __forceinline__ void gemm128_pre(const float* __restrict__ As,
                                            const float* __restrict__ Bs,
                                            float c[2][8][4], int wm, int wn, int g, int t) {
#pragma unroll
    for (int kk = 0; kk < 128; kk += 8) {
        uint32_t a[2][4];
#pragma unroll
        for (int mi = 0; mi < 2; mi++) {
            int r0 = wm * 32 + mi * 16;
            a[mi][0] = f2tf32(As[(r0 + g) * LDA + kk + t]);
            a[mi][1] = f2tf32(As[(r0 + g + 8) * LDA + kk + t]);
            a[mi][2] = f2tf32(As[(r0 + g) * LDA + kk + t + 4]);
            a[mi][3] = f2tf32(As[(r0 + g + 8) * LDA + kk + t + 4]);
        }
#pragma unroll
        for (int ni = 0; ni < 8; ni++) {
            uint32_t b[2];
            int col = wn * 64 + ni * 8 + g;
            b[0] = __float_as_uint(Bs[(kk + t) * LDB + col]);
            b[1] = __float_as_uint(Bs[(kk + t + 4) * LDB + col]);
            mma_tf32(c[0][ni], a[0], b);
            mma_tf32(c[1][ni], a[1], b);
        }
    }
}

__device__ __forceinline__ void fill_tile_f32_pre(float* dst, const float* src,
                                                  int rows_valid, int tid) {
    for (int i = tid; i < 128 * 32; i += NT_PRE) {
        int r = i >> 5, c4 = (i & 31) << 2;
        float4 v = make_float4(0.f, 0.f, 0.f, 0.f);
        if (r < rows_valid) v = *(const float4*)(src + (size_t)r * DIM + c4);
        *(float4*)(dst + r * LDA + c4) = v;
    }
}

__device__ __forceinline__ void fill_w_tf32_pre(float* dst, const float* src, int tid) {
    for (int i = tid; i < 128 * 32; i += NT_PRE) {
        int r = i >> 5, c4 = (i & 31) << 2;
        float4 v = *(const float4*)(src + (size_t)r * DIM + c4);
        v.x = __uint_as_float(f2tf32(v.x));
        v.y = __uint_as_float(f2tf32(v.y));
        v.z = __uint_as_float(f2tf32(v.z));
        v.w = __uint_as_float(f2tf32(v.w));
        *(float4*)(dst + r * LDB + c4) = v;
    }
}

__global__ void __launch_bounds__(NT_PRE, 1)
precompute_pq(const float* __restrict__ nfeat, const float* __restrict__ W1, int N) {
    extern __shared__ float sm[];
    float* As = sm;                 // 128 x LDA
    float* Bs = sm + 128 * LDA;     // 128 x LDB

    int tid = threadIdx.x;
    int lane = tid & 31, w = tid >> 5;
    int wm = w & 3, wn = w >> 2, g = lane >> 2, t = lane & 3;
    int n0 = blockIdx.x * TILE;
    int valid = min(TILE, N - n0);

    fill_tile_f32_pre(As, nfeat + (size_t)n0 * DIM, valid, tid);
    fill_w_tf32_pre(Bs, W1 + 128 * DIM, tid);  // W1b
    __syncthreads();

    float c[2][8][4];
#pragma unroll
    for (int mi = 0; mi < 2; mi++)
#pragma unroll
        for (int ni = 0; ni < 8; ni++)
#pragma unroll
            for (int j = 0; j < 4; j++) c[mi][ni][j] = 0.f;
    gemm128_pre(As, Bs, c, wm, wn, g, t);

    float* P = g_P + (size_t)n0 * DIM;
#pragma unroll
    for (int mi = 0; mi < 2; mi++)
#pragma unroll
        for (int h = 0; h < 2; h++) {
            int r = wm * 32 + mi * 16 + g + h * 8;
#pragma unroll
            for (int ni = 0; ni < 8; ni++) {
                int col = wn * 64 + ni * 8 + 2 * t;
                *(float2*)(P + (size_t)r * DIM + col) =
                    make_float2(c[mi][ni][h * 2], c[mi][ni][h * 2 + 1]);
            }
        }

    __syncthreads();
    fill_w_tf32_pre(Bs, W1 + 256 * DIM, tid);   // W1c
    __syncthreads();

#pragma unroll
    for (int mi = 0; mi < 2; mi++)
#pragma unroll
        for (int ni = 0; ni < 8; ni++)
#pragma unroll
            for (int j = 0; j < 4; j++) c[mi][ni][j] = 0.f;
    gemm128_pre(As, Bs, c, wm, wn, g, t);

    float* Q = g_Q + (size_t)n0 * DIM;
#pragma unroll
    for (int mi = 0; mi < 2; mi++)
#pragma unroll
        for (int h = 0; h < 2; h++) {
            int r = wm * 32 + mi * 16 + g + h * 8;
#pragma unroll
            for (int ni = 0; ni < 8; ni++) {
                int col = wn * 64 + ni * 8 + 2 * t;
                *(float2*)(Q + (size_t)r * DIM + col) =
                    make_float2(c[mi][ni][h * 2], c[mi][ni][h * 2 + 1]);
            }
        }
}

// ===========================================================================
// Persistent fp16 edge kernel.
// smem layout (bytes):
//   T  [0, 34816)         : 128 x 68 half2 — efeat tile, then h tile
//   B1 [34816, 69632)     : W1a transposed n-major half (128 cols x 136 halves)
//   B2 [69632, 104448)    : W2 transposed
//   S  [104448, 172032)   : 128 x 132 fp32 — PQ staging
//   tail [172032, 179200) : idx + params + LN scratch
// ===========================================================================
#define OFF_T    0
#define OFF_B1   34816
#define OFF_B2   69632
#define OFF_S    104448
#define OFF_TAIL 172032
#define SMEM_EDGE 179200

__device__ __forceinline__ uint32_t h2bits(float x, float y) {
    __half2 h = __floats2half2_rn(x, y);
    return *reinterpret_cast<uint32_t*>(&h);
}

// One-time transposed weight fill: dst[n][k] = W[k][n] as half. Pitch 136 halves.
__device__ __forceinline__ void fill_w_half_T(__half* dst, const float* __restrict__ W,
                                              int tid) {
    for (int i = tid; i < 128 * 32; i += NT_EDGE) {
        int k = i >> 5, n4 = (i & 31) << 2;
        float4 v = *(const float4*)(W + k * DIM + n4);
        dst[(n4 + 0) * 136 + k] = __float2half(v.x);
        dst[(n4 + 1) * 136 + k] = __float2half(v.y);
        dst[(n4 + 2) * 136 + k] = __float2half(v.z);
        dst[(n4 + 3) * 136 + k] = __float2half(v.w);
    }
}

// m16n8k16 fp16 GEMM over K=128, 16x32 warp tile.
// A2: row-major half2 (pitch LDH). B2: n-major half2 (pitch LDH).
// c[ni][j]: row = wm*16 + g + (j>=2?8:0), col = wn*32 + ni*8 + 2t + (j&1).
__device__ __forceinline__ void gemm_f16(const uint32_t* __restrict__ A2,
                                         const uint32_t* __restrict__ B2,
                                         float c[4][4], int wm, int wn, int g, int t) {
#pragma unroll
    for (int kp = 0; kp < 64; kp += 8) {   // half2-pair index; each step = K16
        uint32_t a[4];
        const uint32_t* pa0 = A2 + (wm * 16 + g) * LDH + kp + t;
        const uint32_t* pa1 = A2 + (wm * 16 + g + 8) * LDH + kp + t;
        a[0] = pa0[0];
        a[1] = pa1[0];
        a[2] = pa0[4];
        a[3] = pa1[4];
#pragma unroll
        for (int ni = 0; ni < 4; ni++) {
            int col = wn * 32 + ni * 8 + g;
            uint32_t b0 = B2[col * LDH + kp + t];
            uint32_t b1 = B2[col * LDH + kp + t + 4];
            asm volatile(
                "mma.sync.aligned.m16n8k16.row.col.f32.f16.f16.f32 "
                "{%0,%1,%2,%3}, {%4,%5,%6,%7}, {%8,%9}, {%0,%1,%2,%3};\n"
                : "+f"(c[ni][0]), "+f"(c[ni][1]), "+f"(c[ni][2]), "+f"(c[ni][3])
                : "r"(a[0]), "r"(a[1]), "r"(a[2]), "r"(a[3]), "r"(b0), "r"(b1));
        }
    }
}

__global__ void __launch_bounds__(NT_EDGE, 1)
edge_mlp_pers(const float* __restrict__ efeat, const float* __restrict__ W1,
              const float* __restrict__ b1, const float* __restrict__ W2,
              const float* __restrict__ b2, const float* __restrict__ lng,
              const float* __restrict__ lnb, const int* __restrict__ src_idx,
              const int* __restrict__ dst_idx, float* __restrict__ out,
              int E, int N, int nTiles) {
    extern __shared__ char smem[];
    uint32_t* T  = (uint32_t*)(smem + OFF_T);
    uint32_t* B1s = (uint32_t*)(smem + OFF_B1);
    uint32_t* B2s = (uint32_t*)(smem + OFF_B2);
    float* S = (float*)(smem + OFF_S);
    int*   s_src = (int*)(smem + OFF_TAIL);     // 512 B
    int*   s_dst = s_src + 128;                 // 512 B
    float* s_b1  = (float*)(s_dst + 128);       // 512 B
    float* s_b2  = s_b1 + 128;                  // 512 B
    float* s_lng = s_b2 + 128;                  // 512 B
    float* s_lnb = s_lng + 128;                 // 512 B
    float* s_sum = s_lnb + 128;                 // [4][128] -> 2048 B
    float* s_ssq = s_sum + 512;                 // [4][128] -> 2048 B

    int tid = threadIdx.x;
    int lane = tid & 31, w = tid >> 5;
    int wm = w & 7, wn = w >> 3, g = lane >> 2, t = lane & 3;

    // ---- one-time setup (visible to all before first GEMM via tile syncs) ----
    fill_w_half_T((__half*)B1s, W1, tid);   // W1a rows 0..127
    fill_w_half_T((__half*)B2s, W2, tid);
    if (tid < 128) {
        s_b1[tid]  = b1[tid];
        s_b2[tid]  = b2[tid];
        s_lng[tid] = lng[tid];
        s_lnb[tid] = lnb[tid];
    }

    for (int tile = blockIdx.x; tile < nTiles; tile += gridDim.x) {
        int e0 = tile * TILE;
        int valid = min(TILE, E - e0);

        // phase A: per-tile indices + efeat -> T (half2)
        if (tid < 128) {
            int e = e0 + tid;
            int si = (tid < valid) ? src_idx[e] : 0;
            int di = (tid < valid) ? dst_idx[e] : 0;
            s_src[tid] = (si >= 0 && si < N) ? si : 0;
            s_dst[tid] = (di >= 0 && di < N) ? di : 0;
        }
        for (int i = tid; i < 128 * 32; i += NT_EDGE) {
            int r = i >> 5, c4 = (i & 31) << 2;
            float4 v = make_float4(0.f, 0.f, 0.f, 0.f);
            if (r < valid) v = *(const float4*)(efeat + (size_t)(e0 + r) * DIM + c4);
            uint2 u;
            u.x = h2bits(v.x, v.y);
            u.y = h2bits(v.z, v.w);
            *(uint2*)(smem + OFF_T + r * 272 + (i & 31) * 8) = u;
        }
        __syncthreads();   // 1: idx + T ready

        // phase B: S = P[src] + Q[dst] + b1 (fp32)
        for (int i = tid; i < 128 * 32; i += NT_EDGE) {
            int r = i >> 5, c4 = (i & 31) << 2;
            float4 p = *(const float4*)(g_P + (size_t)s_src[r] * DIM + c4);
            float4 q = *(const float4*)(g_Q + (size_t)s_dst[r] * DIM + c4);
            float4 bb = *(const float4*)(s_b1 + c4);
            float4 v;
            v.x = p.x + q.x + bb.x;
            v.y = p.y + q.y + bb.y;
            v.z = p.z + q.z + bb.z;
            v.w = p.w + q.w + bb.w;
            *(float4*)(S + r * LDA + c4) = v;
        }
        __syncthreads();   // 2: S ready (also orders first-tile weight fill)

        // GEMM1: c = efeat_tile @ W1a
        float c[4][4];
#pragma unroll
        for (int ni = 0; ni < 4; ni++)
#pragma unroll
            for (int j = 0; j < 4; j++) c[ni][j] = 0.f;
        gemm_f16(T, B1s, c, wm, wn, g, t);
        __syncthreads();   // 3: all T reads done

        // silu(c + S) -> T as half2 at owned positions
#pragma unroll
        for (int ni = 0; ni < 4; ni++)
#pragma unroll
            for (int h = 0; h < 2; h++) {
                int r = wm * 16 + g + h * 8;
                int col = wn * 32 + ni * 8 + 2 * t;
                float2 pq = *(float2*)(S + r * LDA + col);
                float x0 = c[ni][h * 2] + pq.x;
                float x1 = c[ni][h * 2 + 1] + pq.y;
                float s0 = x0 / (1.f + __expf(-x0));
                float s1 = x1 / (1.f + __expf(-x1));
                T[r * LDH + (col >> 1)] = h2bits(s0, s1);
            }
        __syncthreads();   // 4: h tile complete

        // GEMM2: c = h @ W2
#pragma unroll
        for (int ni = 0; ni < 4; ni++)
#pragma unroll
            for (int j = 0; j < 4; j++) c[ni][j] = 0.f;
        gemm_f16(T, B2s, c, wm, wn, g, t);

        // + b2, LN partial sums
        float psum[2] = {0.f, 0.f};
        float pssq[2] = {0.f, 0.f};
#pragma unroll
        for (int ni = 0; ni < 4; ni++)
#pragma unroll
            for (int j = 0; j < 4; j++) {
                int col = wn * 32 + ni * 8 + 2 * t + (j & 1);
                float v = c[ni][j] + s_b2[col];
                c[ni][j] = v;
                psum[j >> 1] += v;
                pssq[j >> 1] += v * v;
            }
#pragma unroll
        for (int h = 0; h < 2; h++) {
            float s = psum[h], q = pssq[h];
            s += __shfl_xor_sync(0xffffffffu, s, 1);
            s += __shfl_xor_sync(0xffffffffu, s, 2);
            q += __shfl_xor_sync(0xffffffffu, q, 1);
            q += __shfl_xor_sync(0xffffffffu, q, 2);
            if (t == 0) {
                int r = wm * 16 + g + h * 8;
                s_sum[wn * 128 + r] = s;
                s_ssq[wn * 128 + r] = q;
            }
        }
        __syncthreads();   // 5: LN sums ready

        // epilogue: LN, scale/shift, residual (efeat re-read from global), store
#pragma unroll
        for (int h = 0; h < 2; h++) {
            int r = wm * 16 + g + h * 8;
            float sum = s_sum[r] + s_sum[128 + r] + s_sum[256 + r] + s_sum[384 + r];
            float ssq = s_ssq[r] + s_ssq[128 + r] + s_ssq[256 + r] + s_ssq[384 + r];
            float mean = sum * (1.f / 128.f);
            float var = ssq * (1.f / 128.f) - mean * mean;
            float rstd = rsqrtf(var + 1e-5f);
            if (r < valid) {
                const float* erow = efeat + (size_t)(e0 + r) * DIM;
                float* orow = out + (size_t)(e0 + r) * DIM;
#pragma unroll
                for (int ni = 0; ni < 4; ni++) {
                    int col = wn * 32 + ni * 8 + 2 * t;
                    float2 ef = *(const float2*)(erow + col);
                    float y0 = (c[ni][h * 2] - mean) * rstd * s_lng[col] +
                               s_lnb[col] + ef.x;
                    float y1 = (c[ni][h * 2 + 1] - mean) * rstd * s_lng[col + 1] +
                               s_lnb[col + 1] + ef.y;
                    *(float2*)(orow + col) = make_float2(y0, y1);
                }
            }
        }
        // no trailing sync needed: next iter's phase-A writes (s_src, T) are
        // disjoint from epilogue reads (s_sum/s_ssq/params/globals), and sync 1
        // of the next iteration orders everything else.
    }
}

// ===========================================================================
// Launch: size-based input identification (robust to metadata ordering)
// ===========================================================================
extern "C" void kernel_launch(void* const* d_in, const int* in_sizes, int n_in,
                              void* d_out, int out_size) {
    long long maxsz = 0;
    for (int i = 0; i < n_in; i++)
        if ((long long)in_sizes[i] > maxsz) maxsz = in_sizes[i];
    long long E = maxsz / DIM;

    int i_efeat = -1, i_nfeat = -1, i_W1 = -1, i_W2 = -1;
    int idxArr[2] = {-1, -1};  int nIdx = 0;
    int vecArr[4] = {-1, -1, -1, -1}; int nVec = 0;
    for (int i = 0; i < n_in; i++) {
        long long s = in_sizes[i];
        if (s == maxsz)              i_efeat = i;
        else if (s == 3 * 128 * 128) i_W1 = i;
        else if (s == 128 * 128)     i_W2 = i;
        else if (s == 128)           { if (nVec < 4) vecArr[nVec++] = i; }
        else if (s == E)             { if (nIdx < 2) idxArr[nIdx++] = i; }
        else                         i_nfeat = i;
    }
    bool alpha = (i_W1 == 0);
    int i_src = alpha ? idxArr[1] : idxArr[0];
    int i_dst = alpha ? idxArr[0] : idxArr[1];
    int i_b1 = vecArr[0], i_b2 = vecArr[1];
    int i_lng = alpha ? vecArr[3] : vecArr[2];
    int i_lnb = alpha ? vecArr[2] : vecArr[3];

    const float* efeat = (const float*)d_in[i_efeat];
    const float* nfeat = (const float*)d_in[i_nfeat];
    const int* src_idx = (const int*)d_in[i_src];
    const int* dst_idx = (const int*)d_in[i_dst];
    const float* W1 = (const float*)d_in[i_W1];
    const float* b1 = (const float*)d_in[i_b1];
    const float* W2 = (const float*)d_in[i_W2];
    const float* b2 = (const float*)d_in[i_b2];
    const float* lng = (const float*)d_in[i_lng];
    const float* lnb = (const float*)d_in[i_lnb];
    float* out = (float*)d_out;

    int Ei = (int)E;
    int N = in_sizes[i_nfeat] / DIM;

    const int SMEM_A = (128 * LDA + 128 * LDB) * (int)sizeof(float);  // 137216 B

    cudaFuncSetAttribute(precompute_pq, cudaFuncAttributeMaxDynamicSharedMemorySize, SMEM_A);
    cudaFuncSetAttribute(edge_mlp_pers, cudaFuncAttributeMaxDynamicSharedMemorySize,
                         SMEM_EDGE);

    int nBlocks = (N + TILE - 1) / TILE;
    if ((long long)nBlocks * TILE > N_PAD_ROWS) nBlocks = N_PAD_ROWS / TILE;

    int nTiles = (Ei + TILE - 1) / TILE;
    int grid = nTiles < 148 ? nTiles : 148;

    precompute_pq<<<nBlocks, NT_PRE, SMEM_A>>>(nfeat, W1, N);
    edge_mlp_pers<<<grid, NT_EDGE, SMEM_EDGE>>>(
        efeat, W1, b1, W2, b2, lng, lnb, src_idx, dst_idx, out, Ei, N, nTiles);

    long long need = E * DIM + (long long)N * DIM;
    if ((long long)out_size >= need) {
        cudaMemcpyAsync(out + (size_t)E * DIM, nfeat,
                        (size_t)N * DIM * sizeof(float), cudaMemcpyDeviceToDevice);
    }
}